// round 1
// baseline (speedup 1.0000x reference)
#include <cuda_runtime.h>
#include <math.h>

#define N_NET 16
#define HID   32

// Scratch for the 2 broadcast probabilities (device global: allocation-free).
__device__ float2 g_probs;

// Kernel 1: one block, 16 warps. Warp k evaluates MLP k on s[0][k%4],
// then thread 0 reduces to the 2-way softmax.
__global__ __launch_bounds__(512, 1)
void controller_compute_kernel(const float* __restrict__ s,
                               const float* __restrict__ W1,
                               const float* __restrict__ b1,
                               const float* __restrict__ W2,
                               const float* __restrict__ b2,
                               const float* __restrict__ W3,
                               const float* __restrict__ b3)
{
    __shared__ float smem_m[N_NET];

    const int tid  = threadIdx.x;
    const int k    = tid >> 5;   // network id  = warp id
    const int lane = tid & 31;   // output unit = lane id

    // Input scalar for this network: s[batch 0][k % 4]
    const float x = s[k & 3];

    // Layer 1: h1[lane] = relu(x * W1[k,0,lane] + b1[k,lane])
    const float h1 = fmaxf(x * W1[k * HID + lane] + b1[k * HID + lane], 0.0f);

    // Layer 2: h2[lane] = relu( sum_i h1[i] * W2[k,i,lane] + b2[k,lane] )
    // W2[k][i][o] with o = lane -> consecutive addresses across the warp.
    const float* W2k = W2 + k * HID * HID + lane;
    float acc = b2[k * HID + lane];
    #pragma unroll
    for (int i = 0; i < HID; ++i) {
        const float h1_i = __shfl_sync(0xFFFFFFFFu, h1, i);
        acc = fmaf(h1_i, W2k[i * HID], acc);
    }
    const float h2 = fmaxf(acc, 0.0f);

    // Layer 3: warp-reduce h2 . W3[k,:,0]
    float t = h2 * W3[k * HID + lane];
    #pragma unroll
    for (int off = 16; off > 0; off >>= 1)
        t += __shfl_xor_sync(0xFFFFFFFFu, t, off);

    if (lane == 0) {
        const float z = t + b3[k];
        smem_m[k] = 1.0f / (1.0f + __expf(-z));   // sigmoid
    }
    __syncthreads();

    if (tid == 0) {
        // strengths[a] = mean over 8 memberships (2 rules x 4 memberships)
        float s0 = 0.0f, s1 = 0.0f;
        #pragma unroll
        for (int i = 0; i < 8; ++i) { s0 += smem_m[i]; s1 += smem_m[8 + i]; }
        s0 *= 0.125f;
        s1 *= 0.125f;
        // 2-way softmax (numerically safe)
        const float mx = fmaxf(s0, s1);
        const float e0 = __expf(s0 - mx);
        const float e1 = __expf(s1 - mx);
        const float inv = 1.0f / (e0 + e1);
        g_probs = make_float2(e0 * inv, e1 * inv);
    }
}

// Kernel 2: broadcast-fill (B,2) with (p0,p1). One float4 per thread.
__global__ __launch_bounds__(256, 8)
void controller_fill_kernel(float4* __restrict__ out, int n_vec4)
{
    const int idx = blockIdx.x * blockDim.x + threadIdx.x;
    if (idx >= n_vec4) return;
    const float2 p = g_probs;
    out[idx] = make_float4(p.x, p.y, p.x, p.y);
}

extern "C" void kernel_launch(void* const* d_in, const int* in_sizes, int n_in,
                              void* d_out, int out_size)
{
    const float* s  = (const float*)d_in[0];
    const float* W1 = (const float*)d_in[1];
    const float* b1 = (const float*)d_in[2];
    const float* W2 = (const float*)d_in[3];
    const float* b2 = (const float*)d_in[4];
    const float* W3 = (const float*)d_in[5];
    const float* b3 = (const float*)d_in[6];
    float* out = (float*)d_out;

    controller_compute_kernel<<<1, 512>>>(s, W1, b1, W2, b2, W3, b3);

    const int n_vec4 = out_size / 4;   // out_size = B*2, divisible by 4 (B = 262144)
    const int threads = 256;
    const int blocks = (n_vec4 + threads - 1) / threads;
    controller_fill_kernel<<<blocks, threads>>>((float4*)out, n_vec4);
}

// round 2
// speedup vs baseline: 1.2064x; 1.2064x over previous
#include <cuda_runtime.h>
#include <math.h>

#define N_NET 16
#define HID   32

// Fused kernel: every block (1) redundantly evaluates the 16 tiny MLPs on
// s[0], reduces to the 2-way softmax, and (2) fills its contiguous slice of
// the (B,2) output with (p0,p1). One wave: 128 blocks x 512 threads.
// Each thread writes 2 float4s -> 128*512*2 = 131072 float4s = 262144*2 floats.
__global__ __launch_bounds__(512, 1)
void controller_fused_kernel(const float* __restrict__ s,
                             const float* __restrict__ W1,
                             const float* __restrict__ b1,
                             const float* __restrict__ W2,
                             const float* __restrict__ b2,
                             const float* __restrict__ W3,
                             const float* __restrict__ b3,
                             float4* __restrict__ out,
                             int n_vec4)
{
    __shared__ float smem_m[N_NET];

    const int tid  = threadIdx.x;
    const int k    = tid >> 5;   // network id = warp id (0..15)
    const int lane = tid & 31;   // hidden unit = lane id

    // ---- compute phase (all 16 warps active) ----
    // Input scalar for network k: s[batch 0][k % 4]
    const float x = s[k & 3];

    // Layer 1: h1[lane] = relu(x * W1[k,0,lane] + b1[k,lane])
    const float h1 = fmaxf(fmaf(x, W1[k * HID + lane], b1[k * HID + lane]), 0.0f);

    // Layer 2: h2[lane] = relu( sum_i h1[i] * W2[k,i,lane] + b2[k,lane] )
    // W2[k][i][lane] is lane-contiguous -> coalesced loads.
    const float* W2k = W2 + k * HID * HID + lane;
    float acc = b2[k * HID + lane];
    #pragma unroll
    for (int i = 0; i < HID; ++i) {
        const float h1_i = __shfl_sync(0xFFFFFFFFu, h1, i);
        acc = fmaf(h1_i, W2k[i * HID], acc);
    }
    const float h2 = fmaxf(acc, 0.0f);

    // Layer 3: warp-reduce h2 . W3[k,:,0]
    float t = h2 * W3[k * HID + lane];
    #pragma unroll
    for (int off = 16; off > 0; off >>= 1)
        t += __shfl_xor_sync(0xFFFFFFFFu, t, off);

    if (lane == 0) {
        const float z = t + b3[k];
        smem_m[k] = 1.0f / (1.0f + __expf(-z));   // sigmoid
    }
    __syncthreads();

    // ---- every thread derives the softmax locally (cheap, no extra sync) ----
    float s0 = 0.0f, s1 = 0.0f;
    #pragma unroll
    for (int i = 0; i < 8; ++i) { s0 += smem_m[i]; s1 += smem_m[8 + i]; }
    s0 *= 0.125f;
    s1 *= 0.125f;
    const float mx  = fmaxf(s0, s1);
    const float e0  = __expf(s0 - mx);
    const float e1  = __expf(s1 - mx);
    const float inv = 1.0f / (e0 + e1);
    const float4 v = make_float4(e0 * inv, e1 * inv, e0 * inv, e1 * inv);

    // ---- fill phase: 2 consecutive float4s per thread (32B, coalesced) ----
    int base = (blockIdx.x * blockDim.x + tid) * 2;
    if (base < n_vec4)     out[base]     = v;
    if (base + 1 < n_vec4) out[base + 1] = v;
}

extern "C" void kernel_launch(void* const* d_in, const int* in_sizes, int n_in,
                              void* d_out, int out_size)
{
    const float* s  = (const float*)d_in[0];
    const float* W1 = (const float*)d_in[1];
    const float* b1 = (const float*)d_in[2];
    const float* W2 = (const float*)d_in[3];
    const float* b2 = (const float*)d_in[4];
    const float* W3 = (const float*)d_in[5];
    const float* b3 = (const float*)d_in[6];

    const int n_vec4 = out_size / 4;           // 131072 for B=262144
    // 512 threads/block, 2 float4 per thread -> 1024 float4 per block
    const int blocks = (n_vec4 + 1023) / 1024; // 128 -> single wave on 148 SMs

    controller_fused_kernel<<<blocks, 512>>>(s, W1, b1, W2, b2, W3, b3,
                                             (float4*)d_out, n_vec4);
}